// round 2
// baseline (speedup 1.0000x reference)
#include <cuda_runtime.h>
#include <cstdint>

#define S_LEN 1024
#define B_SZ  64
#define H_DIM 512

// Scratch (allocation-free rule: __device__ globals)
__device__ float g_lin[(size_t)S_LEN * B_SZ * H_DIM];  // GEMM output / scan input
__device__ float g_y0 [(size_t)S_LEN * B_SZ * H_DIM];  // layer-1 scan output

// ---------------------------------------------------------------------------
// helpers
// ---------------------------------------------------------------------------
__device__ __forceinline__ float cvt_tf32(float x) {
    uint32_t u;
    asm("cvt.rna.tf32.f32 %0, %1;" : "=r"(u) : "f"(x));
    return __uint_as_float(u);
}

__device__ __forceinline__ void mma_tf32(float* d, const uint32_t* a, const uint32_t* b) {
    asm volatile(
        "mma.sync.aligned.m16n8k8.row.col.f32.tf32.tf32.f32 "
        "{%0,%1,%2,%3}, {%4,%5,%6,%7}, {%8,%9}, {%0,%1,%2,%3};\n"
        : "+f"(d[0]), "+f"(d[1]), "+f"(d[2]), "+f"(d[3])
        : "r"(a[0]), "r"(a[1]), "r"(a[2]), "r"(a[3]),
          "r"(b[0]), "r"(b[1]));
}

// ---------------------------------------------------------------------------
// GEMM (tf32x3 error-compensated):
//   C[m][n] = sum_k A[m][k]*W[n][k] + bias[n], near-fp32 accuracy
// A: (M,512) row-major, W: (512,512) row-major, C: (M,512)
// BM=128, BN=64, BK=16; 256 threads (8 warps, 4x2), warp tile 32x32
// grid: (N/BN, M/BM)  -- N fastest so blocks sharing an A-slice are co-resident
// ---------------------------------------------------------------------------
__global__ __launch_bounds__(256) void gemm_tf32x3_kernel(
    const float* __restrict__ A_ext,
    const float* __restrict__ W,
    const float* __restrict__ bias,
    int use_y0, int M)
{
    const int K = H_DIM, N = H_DIM;
    const int BM = 128, BN = 64, BK = 16;
    const int PAD = 20;  // row stride in floats (16 + 4 pad)

    __shared__ float As_hi[128][PAD];
    __shared__ float As_lo[128][PAD];
    __shared__ float Bs_hi[64][PAD];
    __shared__ float Bs_lo[64][PAD];

    const float* A = use_y0 ? g_y0 : A_ext;
    float* C = g_lin;

    int tid  = threadIdx.x;
    int warp = tid >> 5, lane = tid & 31;
    int wm = warp & 3, wn = warp >> 2;
    int n0 = blockIdx.x * BN, m0 = blockIdx.y * BM;
    int r = lane >> 2, c = lane & 3;

    float acc[2][4][4];
#pragma unroll
    for (int mt = 0; mt < 2; mt++)
#pragma unroll
        for (int nt = 0; nt < 4; nt++)
#pragma unroll
            for (int i = 0; i < 4; i++) acc[mt][nt][i] = 0.0f;

    const float* Ab = A + (size_t)m0 * K;
    const float* Wb = W + (size_t)n0 * K;

    for (int kt = 0; kt < K; kt += BK) {
        // A tile: 128x16 floats = 512 float4; 2 per thread
#pragma unroll
        for (int i = 0; i < 2; i++) {
            int f4  = tid + i * 256;
            int row = f4 >> 2;
            int col = (f4 & 3) << 2;
            float4 v = *reinterpret_cast<const float4*>(Ab + (size_t)row * K + kt + col);
            float hx = cvt_tf32(v.x), hy = cvt_tf32(v.y),
                  hz = cvt_tf32(v.z), hw = cvt_tf32(v.w);
            *reinterpret_cast<float4*>(&As_hi[row][col]) = make_float4(hx, hy, hz, hw);
            *reinterpret_cast<float4*>(&As_lo[row][col]) =
                make_float4(cvt_tf32(v.x - hx), cvt_tf32(v.y - hy),
                            cvt_tf32(v.z - hz), cvt_tf32(v.w - hw));
        }
        // B tile: 64x16 floats = 256 float4; 1 per thread
        {
            int f4  = tid;
            int row = f4 >> 2;
            int col = (f4 & 3) << 2;
            float4 v = *reinterpret_cast<const float4*>(Wb + (size_t)row * K + kt + col);
            float hx = cvt_tf32(v.x), hy = cvt_tf32(v.y),
                  hz = cvt_tf32(v.z), hw = cvt_tf32(v.w);
            *reinterpret_cast<float4*>(&Bs_hi[row][col]) = make_float4(hx, hy, hz, hw);
            *reinterpret_cast<float4*>(&Bs_lo[row][col]) =
                make_float4(cvt_tf32(v.x - hx), cvt_tf32(v.y - hy),
                            cvt_tf32(v.z - hz), cvt_tf32(v.w - hw));
        }
        __syncthreads();

#pragma unroll
        for (int kk = 0; kk < BK; kk += 8) {
            uint32_t ah[2][4], al[2][4], bh[4][2], bl[4][2];
#pragma unroll
            for (int mt = 0; mt < 2; mt++) {
                int row = wm * 32 + mt * 16 + r;
                ah[mt][0] = __float_as_uint(As_hi[row    ][kk + c    ]);
                ah[mt][1] = __float_as_uint(As_hi[row + 8][kk + c    ]);
                ah[mt][2] = __float_as_uint(As_hi[row    ][kk + c + 4]);
                ah[mt][3] = __float_as_uint(As_hi[row + 8][kk + c + 4]);
                al[mt][0] = __float_as_uint(As_lo[row    ][kk + c    ]);
                al[mt][1] = __float_as_uint(As_lo[row + 8][kk + c    ]);
                al[mt][2] = __float_as_uint(As_lo[row    ][kk + c + 4]);
                al[mt][3] = __float_as_uint(As_lo[row + 8][kk + c + 4]);
            }
#pragma unroll
            for (int nt = 0; nt < 4; nt++) {
                int nrow = wn * 32 + nt * 8 + r;
                bh[nt][0] = __float_as_uint(Bs_hi[nrow][kk + c    ]);
                bh[nt][1] = __float_as_uint(Bs_hi[nrow][kk + c + 4]);
                bl[nt][0] = __float_as_uint(Bs_lo[nrow][kk + c    ]);
                bl[nt][1] = __float_as_uint(Bs_lo[nrow][kk + c + 4]);
            }
#pragma unroll
            for (int mt = 0; mt < 2; mt++)
#pragma unroll
                for (int nt = 0; nt < 4; nt++) {
                    mma_tf32(acc[mt][nt], al[mt], bh[nt]);  // lo*hi
                    mma_tf32(acc[mt][nt], ah[mt], bl[nt]);  // hi*lo
                    mma_tf32(acc[mt][nt], ah[mt], bh[nt]);  // hi*hi
                }
        }
        __syncthreads();
    }

    // epilogue: add bias, store float2 pairs
#pragma unroll
    for (int mt = 0; mt < 2; mt++) {
#pragma unroll
        for (int nt = 0; nt < 4; nt++) {
            int row = m0 + wm * 32 + mt * 16 + r;
            int col = n0 + wn * 32 + nt * 8 + 2 * c;
            float bx = bias[col], by = bias[col + 1];
            *reinterpret_cast<float2*>(C + (size_t)row * N + col) =
                make_float2(acc[mt][nt][0] + bx, acc[mt][nt][1] + by);
            *reinterpret_cast<float2*>(C + (size_t)(row + 8) * N + col) =
                make_float2(acc[mt][nt][2] + bx, acc[mt][nt][3] + by);
        }
    }
}

// ---------------------------------------------------------------------------
// Scan: one warp per batch row. 16 elements/lane, state in registers.
//   h = lin_t + rec*h; h = relu6(layernorm(h))
// ---------------------------------------------------------------------------
#define SCAN_STEP(scur, CU)                                                        \
  {                                                                                \
    _Pragma("unroll")                                                              \
    for (int j = 0; j < 16; j++) h[j] = fmaf(rc[j], h[j], CU[j]);                  \
    {                                                                              \
      int sp = (scur) + 2; if (sp > S - 1) sp = S - 1;                             \
      const float* p2 = lp + (size_t)sp * stride;                                  \
      _Pragma("unroll")                                                            \
      for (int q = 0; q < 4; q++) {                                                \
        float4 v = *reinterpret_cast<const float4*>(p2 + q * 4);                   \
        CU[q*4+0] = v.x; CU[q*4+1] = v.y; CU[q*4+2] = v.z; CU[q*4+3] = v.w;        \
      }                                                                            \
      if ((scur) + 6 < S)                                                          \
        asm volatile("prefetch.global.L2 [%0];"                                    \
                     :: "l"(lp + (size_t)((scur) + 6) * stride));                  \
    }                                                                              \
    float ts[16], tq[16];                                                          \
    _Pragma("unroll")                                                              \
    for (int j = 0; j < 16; j++) { ts[j] = h[j]; tq[j] = h[j] * h[j]; }            \
    _Pragma("unroll")                                                              \
    for (int w = 8; w >= 1; w >>= 1) {                                             \
      _Pragma("unroll")                                                            \
      for (int j = 0; j < w; j++) { ts[j] += ts[j+w]; tq[j] += tq[j+w]; }          \
    }                                                                              \
    float sum = ts[0], ssq = tq[0];                                                \
    _Pragma("unroll")                                                              \
    for (int off = 16; off >= 1; off >>= 1) {                                      \
      sum += __shfl_xor_sync(0xffffffffu, sum, off);                               \
      ssq += __shfl_xor_sync(0xffffffffu, ssq, off);                               \
    }                                                                              \
    float mean = sum * (1.0f / H_DIM);                                             \
    float var  = fmaf(ssq, 1.0f / H_DIM, -mean * mean);                            \
    float inv  = rsqrtf(var + 1e-6f);                                              \
    _Pragma("unroll")                                                              \
    for (int j = 0; j < 16; j++) {                                                 \
      float o = fmaf((h[j] - mean) * inv, ga[j], bb[j]);                           \
      o = fminf(fmaxf(o, 0.0f), 6.0f);                                             \
      h[j] = o;                                                                    \
    }                                                                              \
    {                                                                              \
      float* yo = yp + (size_t)(scur) * stride;                                    \
      _Pragma("unroll")                                                            \
      for (int q = 0; q < 4; q++)                                                  \
        *reinterpret_cast<float4*>(yo + q * 4) =                                   \
            make_float4(h[q*4], h[q*4+1], h[q*4+2], h[q*4+3]);                     \
    }                                                                              \
  }

__global__ __launch_bounds__(32) void scan_kernel(
    const float* __restrict__ rec,
    const float* __restrict__ g,
    const float* __restrict__ be,
    float* __restrict__ y_ext,
    float* __restrict__ hid,
    int to_y0, int layer, int S)
{
    const int B = B_SZ;
    int b = blockIdx.x, lane = threadIdx.x;
    int base = lane * 16;

    const float* lin = g_lin;
    float* y = to_y0 ? g_y0 : y_ext;

    float rc[16], ga[16], bb[16], h[16];
#pragma unroll
    for (int q = 0; q < 4; q++) {
        float4 v;
        v = *reinterpret_cast<const float4*>(rec + base + q * 4);
        rc[q*4] = v.x; rc[q*4+1] = v.y; rc[q*4+2] = v.z; rc[q*4+3] = v.w;
        v = *reinterpret_cast<const float4*>(g + base + q * 4);
        ga[q*4] = v.x; ga[q*4+1] = v.y; ga[q*4+2] = v.z; ga[q*4+3] = v.w;
        v = *reinterpret_cast<const float4*>(be + base + q * 4);
        bb[q*4] = v.x; bb[q*4+1] = v.y; bb[q*4+2] = v.z; bb[q*4+3] = v.w;
    }
#pragma unroll
    for (int j = 0; j < 16; j++) h[j] = 0.0f;

    const size_t stride = (size_t)B * H_DIM;
    const float* lp = lin + (size_t)b * H_DIM + base;
    float*       yp = y   + (size_t)b * H_DIM + base;

    // depth-2 register pipeline
    float cuA[16], cuB[16];
#pragma unroll
    for (int q = 0; q < 4; q++) {
        float4 v = *reinterpret_cast<const float4*>(lp + q * 4);
        cuA[q*4] = v.x; cuA[q*4+1] = v.y; cuA[q*4+2] = v.z; cuA[q*4+3] = v.w;
        v = *reinterpret_cast<const float4*>(lp + stride + q * 4);
        cuB[q*4] = v.x; cuB[q*4+1] = v.y; cuB[q*4+2] = v.z; cuB[q*4+3] = v.w;
    }

    for (int s = 0; s < S; s += 2) {
        SCAN_STEP(s,     cuA);
        SCAN_STEP(s + 1, cuB);
    }

    // hiddens: ref does cat(dim=-1).view(2,B,H) ->
    // hid[(b>>5)][2*(b&31)+layer][h] = h_last[b][h]
    float* hp = hid + (size_t)(b >> 5) * (B * H_DIM)
                    + (size_t)(2 * (b & 31) + layer) * H_DIM + base;
#pragma unroll
    for (int q = 0; q < 4; q++)
        *reinterpret_cast<float4*>(hp + q * 4) =
            make_float4(h[q*4], h[q*4+1], h[q*4+2], h[q*4+3]);
}

// ---------------------------------------------------------------------------
// launcher
// ---------------------------------------------------------------------------
extern "C" void kernel_launch(void* const* d_in, const int* in_sizes, int n_in,
                              void* d_out, int out_size)
{
    (void)n_in; (void)out_size;
    const float* x    = (const float*)d_in[0];
    const float* W0   = (const float*)d_in[1];
    const float* b0   = (const float*)d_in[2];
    const float* rec0 = (const float*)d_in[3];
    const float* g0   = (const float*)d_in[4];
    const float* be0  = (const float*)d_in[5];
    const float* W1   = (const float*)d_in[6];
    const float* b1   = (const float*)d_in[7];
    const float* rec1 = (const float*)d_in[8];
    const float* g1   = (const float*)d_in[9];
    const float* be1  = (const float*)d_in[10];

    float* out = (float*)d_out;

    int S = in_sizes[0] / (B_SZ * H_DIM);   // 1024
    int M = S * B_SZ;                       // 65536
    float* hid = out + (size_t)S * B_SZ * H_DIM;

    dim3 ggrid(H_DIM / 64, M / 128);        // N fastest -> A reuse in L2

    // layer 1
    gemm_tf32x3_kernel<<<ggrid, 256>>>(x, W0, b0, /*use_y0=*/0, M);
    scan_kernel<<<B_SZ, 32>>>(rec0, g0, be0, /*y_ext=*/nullptr, hid,
                              /*to_y0=*/1, /*layer=*/0, S);
    // layer 2
    gemm_tf32x3_kernel<<<ggrid, 256>>>(nullptr, W1, b1, /*use_y0=*/1, M);
    scan_kernel<<<B_SZ, 32>>>(rec1, g1, be1, /*y_ext=*/out, hid,
                              /*to_y0=*/0, /*layer=*/1, S);
}

// round 4
// speedup vs baseline: 2.1326x; 2.1326x over previous
#include <cuda_runtime.h>
#include <cuda_fp16.h>
#include <cstdint>

#define S_LEN 1024
#define B_SZ  64
#define H_DIM 512

// Scratch (allocation-free rule: __device__ globals)
__device__ float g_lin[(size_t)S_LEN * B_SZ * H_DIM];  // GEMM output / scan input
__device__ float g_y0 [(size_t)S_LEN * B_SZ * H_DIM];  // layer-1 scan output
__device__ int   g_flags[128];                          // per-4-m-tile done counters

#define W_SCALE     1024.0f
#define W_SCALE_INV (1.0f / 1024.0f)

// ---------------------------------------------------------------------------
// helpers
// ---------------------------------------------------------------------------
__device__ __forceinline__ void mma_f16(float* d, const uint32_t* a, const uint32_t* b) {
    asm volatile(
        "mma.sync.aligned.m16n8k16.row.col.f32.f16.f16.f32 "
        "{%0,%1,%2,%3}, {%4,%5,%6,%7}, {%8,%9}, {%0,%1,%2,%3};\n"
        : "+f"(d[0]), "+f"(d[1]), "+f"(d[2]), "+f"(d[3])
        : "r"(a[0]), "r"(a[1]), "r"(a[2]), "r"(a[3]),
          "r"(b[0]), "r"(b[1]));
}

__device__ __forceinline__ uint32_t pack_h2(float a, float b) {
    __half2 h = __floats2half2_rn(a, b);
    return *reinterpret_cast<uint32_t*>(&h);
}

// split v into fp16 hi + fp16 lo (as packed pairs for 2 values)
__device__ __forceinline__ void split2(float x, float y, uint32_t& hi, uint32_t& lo) {
    float hx = __half2float(__float2half_rn(x));
    float hy = __half2float(__float2half_rn(y));
    hi = pack_h2(hx, hy);
    lo = pack_h2(x - hx, y - hy);
}

__device__ __forceinline__ void wait_group(const int* p) {
    int v;
    while (true) {
        asm volatile("ld.acquire.gpu.b32 %0, [%1];" : "=r"(v) : "l"(p) : "memory");
        if (v >= 32) return;
        __nanosleep(128);
    }
}

// ---------------------------------------------------------------------------
// Combined per-layer kernel.
// bids [0,64)     : scan role (one warp per batch row), waits on g_flags
// bids [64,4160)  : GEMM role: C[m][n] = sum_k A[m][k]*W[n][k]  (bias in scan? no:
//                   bias added in epilogue); fp16x3, W pre-scaled by 1024.
// GEMM tile: BM=128, BN=64, BK=32; 8 warps (4x2), warp tile 32x32, m16n8k16.
// ---------------------------------------------------------------------------
__global__ __launch_bounds__(256, 2) void layer_kernel(
    const float* __restrict__ A_ext,
    const float* __restrict__ W,
    const float* __restrict__ bias,
    const float* __restrict__ rec,
    const float* __restrict__ gam,
    const float* __restrict__ bet,
    float* __restrict__ y_ext,
    float* __restrict__ hid,
    int use_y0, int to_y0, int layer)
{
    const int S = S_LEN, B = B_SZ, K = H_DIM, N = H_DIM;

    if (blockIdx.x >= 64) {
        // =================== GEMM role ===================
        __shared__ uint32_t As_hi[128][20];
        __shared__ uint32_t As_lo[128][20];
        __shared__ uint32_t Bs_hi[64][20];
        __shared__ uint32_t Bs_lo[64][20];

        const float* A = use_y0 ? g_y0 : A_ext;
        float* C = g_lin;

        int gb = blockIdx.x - 64;
        int nb = gb & 7;            // n fastest -> A-slice reuse in L2
        int mt = gb >> 3;
        int n0 = nb * 64, m0 = mt * 128;

        int tid  = threadIdx.x;
        int warp = tid >> 5, lane = tid & 31;
        int wm = warp & 3, wn = warp >> 2;
        int r = lane >> 2, c = lane & 3;

        float acc[2][4][4];
#pragma unroll
        for (int mtt = 0; mtt < 2; mtt++)
#pragma unroll
            for (int nt = 0; nt < 4; nt++)
#pragma unroll
                for (int i = 0; i < 4; i++) acc[mtt][nt][i] = 0.0f;

        const float* Ab = A + (size_t)m0 * K;
        const float* Wb = W + (size_t)n0 * K;

        for (int kt = 0; kt < K; kt += 32) {
            // A tile: 128 rows x 32 floats = 1024 float4; 4 per thread
#pragma unroll
            for (int i = 0; i < 4; i++) {
                int idx = tid + i * 256;
                int row = idx >> 3;
                int c4  = idx & 7;
                float4 v = *reinterpret_cast<const float4*>(Ab + (size_t)row * K + kt + c4 * 4);
                uint32_t h0, l0, h1, l1;
                split2(v.x, v.y, h0, l0);
                split2(v.z, v.w, h1, l1);
                As_hi[row][c4 * 2] = h0;  As_hi[row][c4 * 2 + 1] = h1;
                As_lo[row][c4 * 2] = l0;  As_lo[row][c4 * 2 + 1] = l1;
            }
            // W tile: 64 rows x 32 floats = 512 float4; 2 per thread (scaled)
#pragma unroll
            for (int i = 0; i < 2; i++) {
                int idx = tid + i * 256;
                int row = idx >> 3;
                int c4  = idx & 7;
                float4 v = *reinterpret_cast<const float4*>(Wb + (size_t)row * K + kt + c4 * 4);
                uint32_t h0, l0, h1, l1;
                split2(v.x * W_SCALE, v.y * W_SCALE, h0, l0);
                split2(v.z * W_SCALE, v.w * W_SCALE, h1, l1);
                Bs_hi[row][c4 * 2] = h0;  Bs_hi[row][c4 * 2 + 1] = h1;
                Bs_lo[row][c4 * 2] = l0;  Bs_lo[row][c4 * 2 + 1] = l1;
            }
            __syncthreads();

#pragma unroll
            for (int kk = 0; kk < 2; kk++) {
                int kb = kk * 8;
                uint32_t ah[2][4], al[2][4], bh[4][2], bl[4][2];
#pragma unroll
                for (int mtt = 0; mtt < 2; mtt++) {
                    int row = wm * 32 + mtt * 16 + r;
                    ah[mtt][0] = As_hi[row    ][kb + c    ];
                    ah[mtt][1] = As_hi[row + 8][kb + c    ];
                    ah[mtt][2] = As_hi[row    ][kb + c + 4];
                    ah[mtt][3] = As_hi[row + 8][kb + c + 4];
                    al[mtt][0] = As_lo[row    ][kb + c    ];
                    al[mtt][1] = As_lo[row + 8][kb + c    ];
                    al[mtt][2] = As_lo[row    ][kb + c + 4];
                    al[mtt][3] = As_lo[row + 8][kb + c + 4];
                }
#pragma unroll
                for (int nt = 0; nt < 4; nt++) {
                    int nrow = wn * 32 + nt * 8 + r;
                    bh[nt][0] = Bs_hi[nrow][kb + c];
                    bh[nt][1] = Bs_hi[nrow][kb + c + 4];
                    bl[nt][0] = Bs_lo[nrow][kb + c];
                    bl[nt][1] = Bs_lo[nrow][kb + c + 4];
                }
#pragma unroll
                for (int mtt = 0; mtt < 2; mtt++)
#pragma unroll
                    for (int nt = 0; nt < 4; nt++) {
                        mma_f16(acc[mtt][nt], al[mtt], bh[nt]);  // lo*hi
                        mma_f16(acc[mtt][nt], ah[mtt], bl[nt]);  // hi*lo
                        mma_f16(acc[mtt][nt], ah[mtt], bh[nt]);  // hi*hi
                    }
            }
            __syncthreads();
        }

        // epilogue: unscale, add bias, store
#pragma unroll
        for (int mtt = 0; mtt < 2; mtt++) {
#pragma unroll
            for (int nt = 0; nt < 4; nt++) {
                int row = m0 + wm * 32 + mtt * 16 + r;
                int col = n0 + wn * 32 + nt * 8 + 2 * c;
                float bx = bias[col], by = bias[col + 1];
                *reinterpret_cast<float2*>(C + (size_t)row * N + col) = make_float2(
                    fmaf(acc[mtt][nt][0], W_SCALE_INV, bx),
                    fmaf(acc[mtt][nt][1], W_SCALE_INV, by));
                *reinterpret_cast<float2*>(C + (size_t)(row + 8) * N + col) = make_float2(
                    fmaf(acc[mtt][nt][2], W_SCALE_INV, bx),
                    fmaf(acc[mtt][nt][3], W_SCALE_INV, by));
            }
        }

        __syncthreads();
        if (tid == 0) {
            __threadfence();
            atomicAdd(&g_flags[mt >> 2], 1);  // 4 m-tiles x 8 n-blocks = 32
        }
        return;
    }

    // =================== scan role ===================
    if (threadIdx.x >= 32) return;

    int b = blockIdx.x, lane = threadIdx.x;
    int base = lane * 16;

    const float* lin = g_lin;
    float* y = to_y0 ? g_y0 : y_ext;

    float rc[16], ga[16], bb[16], h[16];
#pragma unroll
    for (int q = 0; q < 4; q++) {
        float4 v;
        v = *reinterpret_cast<const float4*>(rec + base + q * 4);
        rc[q*4] = v.x; rc[q*4+1] = v.y; rc[q*4+2] = v.z; rc[q*4+3] = v.w;
        v = *reinterpret_cast<const float4*>(gam + base + q * 4);
        ga[q*4] = v.x; ga[q*4+1] = v.y; ga[q*4+2] = v.z; ga[q*4+3] = v.w;
        v = *reinterpret_cast<const float4*>(bet + base + q * 4);
        bb[q*4] = v.x; bb[q*4+1] = v.y; bb[q*4+2] = v.z; bb[q*4+3] = v.w;
    }
#pragma unroll
    for (int j = 0; j < 16; j++) h[j] = 0.0f;

    const size_t stride = (size_t)B * H_DIM;
    const float* lp = lin + (size_t)b * H_DIM + base;
    float*       yp = y   + (size_t)b * H_DIM + base;

    // wait for first tile group (timesteps 0..7), then prime depth-2 pipeline
    wait_group(&g_flags[0]);
    float cuA[16], cuB[16];
#pragma unroll
    for (int q = 0; q < 4; q++) {
        float4 v = __ldcg(reinterpret_cast<const float4*>(lp + q * 4));
        cuA[q*4] = v.x; cuA[q*4+1] = v.y; cuA[q*4+2] = v.z; cuA[q*4+3] = v.w;
        v = __ldcg(reinterpret_cast<const float4*>(lp + stride + q * 4));
        cuB[q*4] = v.x; cuB[q*4+1] = v.y; cuB[q*4+2] = v.z; cuB[q*4+3] = v.w;
    }

#define SCAN_STEP(scur, CU)                                                        \
  {                                                                                \
    _Pragma("unroll")                                                              \
    for (int j = 0; j < 16; j++) h[j] = fmaf(rc[j], h[j], CU[j]);                  \
    {                                                                              \
      int sp = (scur) + 2;                                                         \
      if (sp < S && (sp & 7) == 0) wait_group(&g_flags[sp >> 3]);                  \
      if (sp > S - 1) sp = S - 1;                                                  \
      const float* p2 = lp + (size_t)sp * stride;                                  \
      _Pragma("unroll")                                                            \
      for (int q = 0; q < 4; q++) {                                                \
        float4 v = __ldcg(reinterpret_cast<const float4*>(p2 + q * 4));            \
        CU[q*4+0] = v.x; CU[q*4+1] = v.y; CU[q*4+2] = v.z; CU[q*4+3] = v.w;        \
      }                                                                            \
    }                                                                              \
    float ts[16], tq[16];                                                          \
    _Pragma("unroll")                                                              \
    for (int j = 0; j < 16; j++) { ts[j] = h[j]; tq[j] = h[j] * h[j]; }            \
    _Pragma("unroll")                                                              \
    for (int w = 8; w >= 1; w >>= 1) {                                             \
      _Pragma("unroll")                                                            \
      for (int j = 0; j < w; j++) { ts[j] += ts[j+w]; tq[j] += tq[j+w]; }          \
    }                                                                              \
    float sum = ts[0], ssq = tq[0];                                                \
    _Pragma("unroll")                                                              \
    for (int off = 16; off >= 1; off >>= 1) {                                      \
      sum += __shfl_xor_sync(0xffffffffu, sum, off);                               \
      ssq += __shfl_xor_sync(0xffffffffu, ssq, off);                               \
    }                                                                              \
    float mean = sum * (1.0f / H_DIM);                                             \
    float var  = fmaf(ssq, 1.0f / H_DIM, -mean * mean);                            \
    float inv  = rsqrtf(var + 1e-6f);                                              \
    _Pragma("unroll")                                                              \
    for (int j = 0; j < 16; j++) {                                                 \
      float o = fmaf((h[j] - mean) * inv, ga[j], bb[j]);                           \
      o = fminf(fmaxf(o, 0.0f), 6.0f);                                             \
      h[j] = o;                                                                    \
    }                                                                              \
    {                                                                              \
      float* yo = yp + (size_t)(scur) * stride;                                    \
      _Pragma("unroll")                                                            \
      for (int q = 0; q < 4; q++)                                                  \
        *reinterpret_cast<float4*>(yo + q * 4) =                                   \
            make_float4(h[q*4], h[q*4+1], h[q*4+2], h[q*4+3]);                     \
    }                                                                              \
  }

    for (int s = 0; s < S; s += 2) {
        SCAN_STEP(s,     cuA);
        SCAN_STEP(s + 1, cuB);
    }

    // hiddens: ref does cat(dim=-1).view(2,B,H) ->
    // hid[(b>>5)][2*(b&31)+layer][h] = h_last[b][h]
    float* hp = hid + (size_t)(b >> 5) * (B * H_DIM)
                    + (size_t)(2 * (b & 31) + layer) * H_DIM + base;
#pragma unroll
    for (int q = 0; q < 4; q++)
        *reinterpret_cast<float4*>(hp + q * 4) =
            make_float4(h[q*4], h[q*4+1], h[q*4+2], h[q*4+3]);
}

// ---------------------------------------------------------------------------
// flag reset (must run before each layer_kernel; graph replays reuse state)
// ---------------------------------------------------------------------------
__global__ void zero_flags_kernel() {
    g_flags[threadIdx.x] = 0;
}

// ---------------------------------------------------------------------------
// launcher
// ---------------------------------------------------------------------------
extern "C" void kernel_launch(void* const* d_in, const int* in_sizes, int n_in,
                              void* d_out, int out_size)
{
    (void)n_in; (void)out_size; (void)in_sizes;
    const float* x    = (const float*)d_in[0];
    const float* W0   = (const float*)d_in[1];
    const float* b0   = (const float*)d_in[2];
    const float* rec0 = (const float*)d_in[3];
    const float* g0   = (const float*)d_in[4];
    const float* be0  = (const float*)d_in[5];
    const float* W1   = (const float*)d_in[6];
    const float* b1   = (const float*)d_in[7];
    const float* rec1 = (const float*)d_in[8];
    const float* g1   = (const float*)d_in[9];
    const float* be1  = (const float*)d_in[10];

    float* out = (float*)d_out;
    float* hid = out + (size_t)S_LEN * B_SZ * H_DIM;

    const int GRID = 64 + (S_LEN * B_SZ / 128) * (H_DIM / 64);  // 64 + 4096

    // layer 1
    zero_flags_kernel<<<1, 128>>>();
    layer_kernel<<<GRID, 256>>>(x, W0, b0, rec0, g0, be0,
                                nullptr, hid, /*use_y0=*/0, /*to_y0=*/1, /*layer=*/0);
    // layer 2
    zero_flags_kernel<<<1, 128>>>();
    layer_kernel<<<GRID, 256>>>(nullptr, W1, b1, rec1, g1, be1,
                                out, hid, /*use_y0=*/1, /*to_y0=*/0, /*layer=*/1);
}